// round 1
// baseline (speedup 1.0000x reference)
#include <cuda_runtime.h>
#include <cuda_bf16.h>
#include <cstdint>

// Embedding row-gather: out[t, :] = weights[ids[t], :]
// ids: int32[16384], weights: float[50257, 1024], out: float[16384, 1024]
// One CTA per token row; 256 threads x float4 = 1024 floats = one full row.

#define EMBED 1024
#define VEC   (EMBED / 4)   // 256 float4 per row

__global__ __launch_bounds__(256) void embed_gather_kernel(
    const int* __restrict__ ids,
    const float4* __restrict__ weights,   // [VOCAB, VEC]
    float4* __restrict__ out,             // [T, VEC]
    int n_tokens)
{
    int t = blockIdx.x;
    if (t >= n_tokens) return;
    int row = ids[t];  // broadcast load, L1-cached across the CTA
    const float4* src = weights + (size_t)row * VEC;
    float4* dst = out + (size_t)t * VEC;
    dst[threadIdx.x] = src[threadIdx.x];
}

extern "C" void kernel_launch(void* const* d_in, const int* in_sizes, int n_in,
                              void* d_out, int out_size) {
    // metadata order: token_ids (int32, 16384), weights (float32, 50257*1024)
    const int* ids = (const int*)d_in[0];
    const float4* w = (const float4*)d_in[1];
    float4* out = (float4*)d_out;
    int n_tokens = in_sizes[0];  // 4 * 4096 = 16384
    embed_gather_kernel<<<n_tokens, 256>>>(ids, w, out, n_tokens);
}

// round 4
// speedup vs baseline: 1.2756x; 1.2756x over previous
#include <cuda_runtime.h>
#include <cuda_bf16.h>
#include <cstdint>

// Embedding row-gather: out[t, :] = weights[ids[t], :]
// ids: int32[16384], weights: float[50257, 1024], out: float[16384, 1024]
//
// R2: 8 rows per CTA, 256 threads. Each thread issues 8 INDEPENDENT LDG.128
// (one chunk from each of 8 gathered rows) before any STG, raising per-warp
// MLP from 1 to 8 so DRAM latency (577 cyc) is amortized and the kernel runs
// at bandwidth rather than latency.

#define EMBED 1024
#define VEC   (EMBED / 4)      // 256 float4 per row
#define ROWS_PER_CTA 8

__global__ __launch_bounds__(256) void embed_gather_kernel(
    const int* __restrict__ ids,
    const float4* __restrict__ weights,   // [VOCAB, VEC]
    float4* __restrict__ out,             // [T, VEC]
    int n_tokens)
{
    int base = blockIdx.x * ROWS_PER_CTA;
    int tid = threadIdx.x;

    // Row indices: broadcast scalar loads (L1/L2 hot, consecutive CTAs share lines)
    int row[ROWS_PER_CTA];
#pragma unroll
    for (int r = 0; r < ROWS_PER_CTA; r++)
        row[r] = ids[base + r];

    // 8 independent gathered loads — batched for MLP
    float4 v[ROWS_PER_CTA];
#pragma unroll
    for (int r = 0; r < ROWS_PER_CTA; r++)
        v[r] = weights[(size_t)row[r] * VEC + tid];

    // 8 coalesced stores
#pragma unroll
    for (int r = 0; r < ROWS_PER_CTA; r++)
        out[(size_t)(base + r) * VEC + tid] = v[r];
}

extern "C" void kernel_launch(void* const* d_in, const int* in_sizes, int n_in,
                              void* d_out, int out_size) {
    const int* ids = (const int*)d_in[0];
    const float4* w = (const float4*)d_in[1];
    float4* out = (float4*)d_out;
    int n_tokens = in_sizes[0];  // 16384, divisible by 8
    int grid = n_tokens / ROWS_PER_CTA;
    embed_gather_kernel<<<grid, 256>>>(ids, w, out, n_tokens);
}

// round 5
// speedup vs baseline: 1.2912x; 1.0122x over previous
#include <cuda_runtime.h>
#include <cuda_bf16.h>
#include <cstdint>

// Embedding row-gather: out[t, :] = weights[ids[t], :]
// ids: int32[16384], weights: float[50257, 1024], out: float[16384, 1024]
//
// R5: same 8-rows-per-CTA shape as R4, but the 8 gathered LDG.128 are issued
// via asm volatile ld.global.nc.v4.f32 — ptxas cannot interleave volatile asm,
// so all 8 loads are front-batched in SASS (true MLP_p1=8) instead of the
// 2-deep ld/st pairing it chose at regs=32.

#define EMBED 1024
#define VEC   (EMBED / 4)      // 256 float4 per row
#define ROWS_PER_CTA 8

__global__ __launch_bounds__(256) void embed_gather_kernel(
    const int* __restrict__ ids,
    const float* __restrict__ weights,    // [VOCAB, EMBED]
    float4* __restrict__ out,             // [T, VEC]
    int n_tokens)
{
    int base = blockIdx.x * ROWS_PER_CTA;
    int tid = threadIdx.x;

    int row[ROWS_PER_CTA];
#pragma unroll
    for (int r = 0; r < ROWS_PER_CTA; r++)
        row[r] = ids[base + r];

    const float* src[ROWS_PER_CTA];
#pragma unroll
    for (int r = 0; r < ROWS_PER_CTA; r++)
        src[r] = weights + (size_t)row[r] * EMBED + tid * 4;

    float vx[ROWS_PER_CTA], vy[ROWS_PER_CTA], vz[ROWS_PER_CTA], vw[ROWS_PER_CTA];

    // 8 consecutive LDG.E.NC.128 — volatile asm is not reordered by ptxas,
    // forcing all 8 loads in flight before any dependent store.
#pragma unroll
    for (int r = 0; r < ROWS_PER_CTA; r++) {
        asm volatile("ld.global.nc.v4.f32 {%0,%1,%2,%3}, [%4];"
                     : "=f"(vx[r]), "=f"(vy[r]), "=f"(vz[r]), "=f"(vw[r])
                     : "l"(src[r]));
    }

#pragma unroll
    for (int r = 0; r < ROWS_PER_CTA; r++) {
        float4 v;
        v.x = vx[r]; v.y = vy[r]; v.z = vz[r]; v.w = vw[r];
        out[(size_t)(base + r) * VEC + tid] = v;
    }
}

extern "C" void kernel_launch(void* const* d_in, const int* in_sizes, int n_in,
                              void* d_out, int out_size) {
    const int* ids = (const int*)d_in[0];
    const float* w = (const float*)d_in[1];
    float4* out = (float4*)d_out;
    int n_tokens = in_sizes[0];  // 16384, divisible by 8
    int grid = n_tokens / ROWS_PER_CTA;
    embed_gather_kernel<<<grid, 256>>>(ids, w, out, n_tokens);
}